// round 1
// baseline (speedup 1.0000x reference)
#include <cuda_runtime.h>
#include <math.h>

// Problem constants (fixed shapes for this dataset)
#define NTOK_MAX 8192
#define E 64
#define TOPK 2

// Scratch (no cudaMalloc allowed): intermediate activations + routing decisions
__device__ float g_h[NTOK_MAX * 4096];        // 128 MB intermediate (post-GELU)
__device__ int   g_eidx_up[NTOK_MAX * 2];
__device__ float g_prob_up[NTOK_MAX * 2];
__device__ int   g_eidx_dn[NTOK_MAX * 2];
__device__ float g_prob_dn[NTOK_MAX * 2];

// ---------------------------------------------------------------------------
// Router: logits = X[N,K] @ W[E,K]^T, then per-token top-2 + softmax(2).
// Block = 64 tokens x 64 experts (all experts -> top-2 fused in-block).
// 256 threads, each computes a 4x4 register tile.
// ---------------------------------------------------------------------------
__global__ void router_kernel(const float* __restrict__ X,
                              const float* __restrict__ W,
                              int K, int phase /*0=up,1=down*/)
{
    __shared__ float Xs[64 * 33];
    __shared__ float Ws[64 * 33];
    __shared__ float Ls[64 * 65];

    const int tid = threadIdx.x;
    const int ty = tid >> 4;      // 0..15
    const int tx = tid & 15;      // 0..15
    const int tok0 = blockIdx.x * 64;

    float acc[4][4];
#pragma unroll
    for (int r = 0; r < 4; r++)
#pragma unroll
        for (int c = 0; c < 4; c++) acc[r][c] = 0.f;

    for (int kt = 0; kt < K; kt += 32) {
#pragma unroll
        for (int i = 0; i < 8; i++) {
            int idx = tid + i * 256;          // 0..2047
            int row = idx >> 5;
            int col = idx & 31;
            Xs[row * 33 + col] = X[(size_t)(tok0 + row) * K + kt + col];
            Ws[row * 33 + col] = W[(size_t)row * K + kt + col];
        }
        __syncthreads();
#pragma unroll
        for (int k = 0; k < 32; k++) {
            float a[4], b[4];
#pragma unroll
            for (int r = 0; r < 4; r++) a[r] = Xs[(ty + 16 * r) * 33 + k];
#pragma unroll
            for (int c = 0; c < 4; c++) b[c] = Ws[(tx + 16 * c) * 33 + k];
#pragma unroll
            for (int r = 0; r < 4; r++)
#pragma unroll
                for (int c = 0; c < 4; c++) acc[r][c] += a[r] * b[c];
        }
        __syncthreads();
    }

#pragma unroll
    for (int r = 0; r < 4; r++)
#pragma unroll
        for (int c = 0; c < 4; c++)
            Ls[(ty + 16 * r) * 65 + (tx + 16 * c)] = acc[r][c];
    __syncthreads();

    if (tid < 64) {
        const float* lrow = &Ls[tid * 65];
        float v0 = -1e30f; int i0 = 0;
#pragma unroll
        for (int e = 0; e < 64; e++) {
            float v = lrow[e];
            if (v > v0) { v0 = v; i0 = e; }
        }
        float v1 = -1e30f; int i1 = 0;
#pragma unroll
        for (int e = 0; e < 64; e++) {
            if (e == i0) continue;
            float v = lrow[e];
            if (v > v1) { v1 = v; i1 = e; }
        }
        // softmax over [v0, v1] (v0 >= v1)
        float p0 = 1.0f / (1.0f + expf(v1 - v0));
        float p1 = 1.0f - p0;
        int n = tok0 + tid;
        int*   ei = phase ? g_eidx_dn : g_eidx_up;
        float* pr = phase ? g_prob_dn : g_prob_up;
        ei[n * 2 + 0] = i0;
        ei[n * 2 + 1] = i1;
        pr[n * 2 + 0] = p0;
        pr[n * 2 + 1] = p1;
    }
}

// ---------------------------------------------------------------------------
// Up layer: per token, Y = sum_k prob_k * (A_e @ X @ B_e^T), X = x row as 32x32.
// A: [E,64,32], B: [E,64,32]. Output: gelu(Y*scale + bias) -> g_h[n, 4096].
// One block per token, 256 threads.
// ---------------------------------------------------------------------------
__global__ void up_kernel(const float* __restrict__ X,
                          const float* __restrict__ A,
                          const float* __restrict__ Bm,
                          const float* __restrict__ scale,
                          const float* __restrict__ bias)
{
    __shared__ float xs[1024];          // X row, [i=32][j=32] stride 32
    __shared__ float Asm[64 * 33];      // A[o][i]
    __shared__ float Bsm[64 * 33];      // B[p][j]
    __shared__ float Tsm[64 * 33];      // T[o][j] (prob-scaled)

    const int tid = threadIdx.x;
    const int n = blockIdx.x;
    const int ty = tid >> 4;
    const int tx = tid & 15;

    // load x row (256 x float4 = 1024 floats)
    ((float4*)xs)[tid] = ((const float4*)(X + (size_t)n * 1024))[tid];

    const float sc = scale[0];
    const int   e0 = g_eidx_up[n * 2],     e1 = g_eidx_up[n * 2 + 1];
    const float p0 = g_prob_up[n * 2],     p1 = g_prob_up[n * 2 + 1];

    float acc[4][4];
#pragma unroll
    for (int r = 0; r < 4; r++)
#pragma unroll
        for (int c = 0; c < 4; c++) acc[r][c] = 0.f;

    __syncthreads();

#pragma unroll 1
    for (int kk = 0; kk < 2; kk++) {
        const int   e = kk ? e1 : e0;
        const float p = kk ? p1 : p0;
        const float* Ag = A  + (size_t)e * 2048;
        const float* Bg = Bm + (size_t)e * 2048;
#pragma unroll
        for (int i = 0; i < 8; i++) {
            int idx = tid + i * 256;
            int row = idx >> 5, col = idx & 31;
            Asm[row * 33 + col] = Ag[idx];
            Bsm[row * 33 + col] = Bg[idx];
        }
        __syncthreads();

        // T[o][j] = p * sum_i A[o][i] * X[i][j] ; o = ty+16r (r<4), j = tx+16c (c<2)
        float t[4][2];
#pragma unroll
        for (int r = 0; r < 4; r++) { t[r][0] = 0.f; t[r][1] = 0.f; }
#pragma unroll
        for (int i = 0; i < 32; i++) {
            float xv0 = xs[i * 32 + tx];
            float xv1 = xs[i * 32 + tx + 16];
#pragma unroll
            for (int r = 0; r < 4; r++) {
                float av = Asm[(ty + 16 * r) * 33 + i];
                t[r][0] += av * xv0;
                t[r][1] += av * xv1;
            }
        }
#pragma unroll
        for (int r = 0; r < 4; r++) {
            Tsm[(ty + 16 * r) * 33 + tx]      = p * t[r][0];
            Tsm[(ty + 16 * r) * 33 + tx + 16] = p * t[r][1];
        }
        __syncthreads();

        // Y[o][pc] += sum_j T[o][j] * B[pc][j] ; o = ty+16r, pc = tx+16c (c<4)
#pragma unroll
        for (int j = 0; j < 32; j++) {
            float a[4], b[4];
#pragma unroll
            for (int r = 0; r < 4; r++) a[r] = Tsm[(ty + 16 * r) * 33 + j];
#pragma unroll
            for (int c = 0; c < 4; c++) b[c] = Bsm[(tx + 16 * c) * 33 + j];
#pragma unroll
            for (int r = 0; r < 4; r++)
#pragma unroll
                for (int c = 0; c < 4; c++) acc[r][c] += a[r] * b[c];
        }
        __syncthreads();
    }

    // epilogue: scale + bias + exact-erf GELU, store to g_h
    float* Hrow = g_h + (size_t)n * 4096;
#pragma unroll
    for (int r = 0; r < 4; r++) {
        int o = ty + 16 * r;
#pragma unroll
        for (int c = 0; c < 4; c++) {
            int pc = tx + 16 * c;
            int oi = o * 64 + pc;
            float y = acc[r][c] * sc + bias[oi];
            Hrow[oi] = 0.5f * y * (1.0f + erff(y * 0.70710678118654752f));
        }
    }
}

// ---------------------------------------------------------------------------
// Down layer: per token, Y = sum_k prob_k * (A_e @ H @ B_e^T), H = h row as 64x64.
// A: [E,32,64], B: [E,32,64]. Output: Y*scale + bias -> out[n, 1024].
// ---------------------------------------------------------------------------
__global__ void down_kernel(const float* __restrict__ A,
                            const float* __restrict__ Bm,
                            const float* __restrict__ scale,
                            const float* __restrict__ bias,
                            float* __restrict__ out)
{
    __shared__ float xs[64 * 65];       // H row, [i=64][j=64] stride 65
    __shared__ float Asm[32 * 65];      // A[o][i] i<64
    __shared__ float Bsm[32 * 65];      // B[p][j] j<64
    __shared__ float Tsm[32 * 65];      // T[o][j]

    const int tid = threadIdx.x;
    const int n = blockIdx.x;
    const int ty = tid >> 4;
    const int tx = tid & 15;

    const float* Xrow = g_h + (size_t)n * 4096;
#pragma unroll
    for (int i = 0; i < 16; i++) {
        int idx = tid + i * 256;
        int row = idx >> 6, col = idx & 63;
        xs[row * 65 + col] = Xrow[idx];
    }

    const float sc = scale[0];
    const int   e0 = g_eidx_dn[n * 2],     e1 = g_eidx_dn[n * 2 + 1];
    const float p0 = g_prob_dn[n * 2],     p1 = g_prob_dn[n * 2 + 1];

    float acc[2][2];
    acc[0][0] = acc[0][1] = acc[1][0] = acc[1][1] = 0.f;

    __syncthreads();

#pragma unroll 1
    for (int kk = 0; kk < 2; kk++) {
        const int   e = kk ? e1 : e0;
        const float p = kk ? p1 : p0;
        const float* Ag = A  + (size_t)e * 2048;
        const float* Bg = Bm + (size_t)e * 2048;
#pragma unroll
        for (int i = 0; i < 8; i++) {
            int idx = tid + i * 256;
            int row = idx >> 6, col = idx & 63;
            Asm[row * 65 + col] = Ag[idx];
            Bsm[row * 65 + col] = Bg[idx];
        }
        __syncthreads();

        // T[o][j] = p * sum_i A[o][i] * H[i][j] ; o = ty+16r (r<2), j = tx+16c (c<4)
        float t[2][4];
#pragma unroll
        for (int r = 0; r < 2; r++)
#pragma unroll
            for (int c = 0; c < 4; c++) t[r][c] = 0.f;
#pragma unroll
        for (int i = 0; i < 64; i++) {
            float xv[4];
#pragma unroll
            for (int c = 0; c < 4; c++) xv[c] = xs[i * 65 + tx + 16 * c];
#pragma unroll
            for (int r = 0; r < 2; r++) {
                float av = Asm[(ty + 16 * r) * 65 + i];
#pragma unroll
                for (int c = 0; c < 4; c++) t[r][c] += av * xv[c];
            }
        }
#pragma unroll
        for (int r = 0; r < 2; r++)
#pragma unroll
            for (int c = 0; c < 4; c++)
                Tsm[(ty + 16 * r) * 65 + tx + 16 * c] = p * t[r][c];
        __syncthreads();

        // Y[o][pc] += sum_j T[o][j] * B[pc][j] ; o = ty+16r, pc = tx+16c (c<2)
#pragma unroll
        for (int j = 0; j < 64; j++) {
            float a[2], b[2];
#pragma unroll
            for (int r = 0; r < 2; r++) a[r] = Tsm[(ty + 16 * r) * 65 + j];
#pragma unroll
            for (int c = 0; c < 2; c++) b[c] = Bsm[(tx + 16 * c) * 65 + j];
#pragma unroll
            for (int r = 0; r < 2; r++)
#pragma unroll
                for (int c = 0; c < 2; c++) acc[r][c] += a[r] * b[c];
        }
        __syncthreads();
    }

    float* orow = out + (size_t)n * 1024;
#pragma unroll
    for (int r = 0; r < 2; r++) {
        int o = ty + 16 * r;
#pragma unroll
        for (int c = 0; c < 2; c++) {
            int pc = tx + 16 * c;
            int oi = o * 32 + pc;
            orow[oi] = acc[r][c] * sc + bias[oi];
        }
    }
}

// ---------------------------------------------------------------------------
extern "C" void kernel_launch(void* const* d_in, const int* in_sizes, int n_in,
                              void* d_out, int out_size)
{
    const float* x        = (const float*)d_in[0];
    const float* W_up     = (const float*)d_in[1];
    const float* A_up     = (const float*)d_in[2];
    const float* B_up     = (const float*)d_in[3];
    const float* scale_up = (const float*)d_in[4];
    const float* bias_up  = (const float*)d_in[5];
    const float* W_dn     = (const float*)d_in[6];
    const float* A_dn     = (const float*)d_in[7];
    const float* B_dn     = (const float*)d_in[8];
    const float* scale_dn = (const float*)d_in[9];
    const float* bias_dn  = (const float*)d_in[10];
    float* out = (float*)d_out;

    const int N = in_sizes[0] / 1024;   // 8192 tokens

    float* hptr = nullptr;
    cudaGetSymbolAddress((void**)&hptr, g_h);

    // up router: logits over x (K=1024), fused top2+softmax
    router_kernel<<<N / 64, 256>>>(x, W_up, 1024, 0);
    // up bilinear + GELU -> g_h
    up_kernel<<<N, 256>>>(x, A_up, B_up, scale_up, bias_up);
    // down router over h (K=4096)
    router_kernel<<<N / 64, 256>>>(hptr, W_dn, 4096, 1);
    // down bilinear -> out
    down_kernel<<<N, 256>>>(A_dn, B_dn, scale_dn, bias_dn, out);
}

// round 4
// speedup vs baseline: 1.2161x; 1.2161x over previous
#include <cuda_runtime.h>
#include <math.h>
#include <stdint.h>

// Fixed shapes for this dataset
#define NTOK_MAX 8192

// Scratch (no cudaMalloc allowed)
__device__ float g_h[NTOK_MAX * 4096];        // 128 MB intermediate (post-GELU)
__device__ int   g_eidx_up[NTOK_MAX * 2];
__device__ float g_prob_up[NTOK_MAX * 2];
__device__ int   g_eidx_dn[NTOK_MAX * 2];
__device__ float g_prob_dn[NTOK_MAX * 2];

// round-to-nearest tf32 kept in float container
__device__ __forceinline__ float tf32r(float f) {
    uint32_t u;
    asm("cvt.rna.tf32.f32 %0, %1;" : "=r"(u) : "f"(f));
    return __uint_as_float(u);
}
__device__ __forceinline__ void split_tf32(float f, float& hi, float& lo) {
    hi = tf32r(f);
    lo = tf32r(f - hi);
}
__device__ __forceinline__ uint32_t FB(float f) { return __float_as_uint(f); }

#define MMA_TF32(C, a0, a1, a2, a3, b0, b1)                                    \
    asm volatile(                                                              \
        "mma.sync.aligned.m16n8k8.row.col.f32.tf32.tf32.f32 "                  \
        "{%0,%1,%2,%3},{%4,%5,%6,%7},{%8,%9},{%0,%1,%2,%3};"                   \
        : "+f"((C)[0]), "+f"((C)[1]), "+f"((C)[2]), "+f"((C)[3])               \
        : "r"(a0), "r"(a1), "r"(a2), "r"(a3), "r"(b0), "r"(b1));

// 3xTF32: hi*hi + hi*lo + lo*hi  (lo*lo negligible)
#define MMA3(C, ah0, ah1, ah2, ah3, al0, al1, al2, al3, bh0, bh1, bl0, bl1)    \
    MMA_TF32(C, ah0, ah1, ah2, ah3, bh0, bh1);                                 \
    MMA_TF32(C, ah0, ah1, ah2, ah3, bl0, bl1);                                 \
    MMA_TF32(C, al0, al1, al2, al3, bh0, bh1);

// ---------------------------------------------------------------------------
// Router: logits = X[N,K] @ W[E,K]^T via 3xTF32 mma, then top-2 + softmax(2).
// Block = 64 tokens x 64 experts. 256 threads = 8 warps.
// dyn smem: XsH(2304) XsL(2304) WsH(2304) WsL(2304) Ls(4160) = 53504 B
// ---------------------------------------------------------------------------
__global__ void router_mma(const float* __restrict__ X,
                           const float* __restrict__ W,
                           int K, int phase)
{
    extern __shared__ float sm[];
    float* XsH = sm;
    float* XsL = sm + 2304;
    float* WsH = sm + 4608;
    float* WsL = sm + 6912;
    float* Ls  = sm + 9216;   // 64*65

    const int tid  = threadIdx.x;
    const int w    = tid >> 5;
    const int lane = tid & 31;
    const int grp  = lane >> 2;
    const int qc   = lane & 3;
    const int tok0 = blockIdx.x * 64;
    const int mtile = w >> 1;
    const int nbase = (w & 1) * 4;

    float c[4][4];
#pragma unroll
    for (int t = 0; t < 4; t++)
#pragma unroll
        for (int q = 0; q < 4; q++) c[t][q] = 0.f;

    for (int kt = 0; kt < K; kt += 32) {
#pragma unroll
        for (int i = 0; i < 8; i++) {
            int idx = tid + i * 256;
            int row = idx >> 5, col = idx & 31;
            float xv = X[(size_t)(tok0 + row) * K + kt + col];
            float wv = W[(size_t)row * K + kt + col];
            split_tf32(xv, XsH[row * 36 + col], XsL[row * 36 + col]);
            split_tf32(wv, WsH[row * 36 + col], WsL[row * 36 + col]);
        }
        __syncthreads();
#pragma unroll
        for (int kk = 0; kk < 4; kk++) {
            int k0 = kk * 8;
            int aoff = (mtile * 16 + grp) * 36 + k0 + qc;
            uint32_t ah0 = FB(XsH[aoff]),      ah1 = FB(XsH[aoff + 8 * 36]);
            uint32_t ah2 = FB(XsH[aoff + 4]),  ah3 = FB(XsH[aoff + 8 * 36 + 4]);
            uint32_t al0 = FB(XsL[aoff]),      al1 = FB(XsL[aoff + 8 * 36]);
            uint32_t al2 = FB(XsL[aoff + 4]),  al3 = FB(XsL[aoff + 8 * 36 + 4]);
#pragma unroll
            for (int t = 0; t < 4; t++) {
                int boff = ((nbase + t) * 8 + grp) * 36 + k0 + qc;
                uint32_t bh0 = FB(WsH[boff]), bh1 = FB(WsH[boff + 4]);
                uint32_t bl0 = FB(WsL[boff]), bl1 = FB(WsL[boff + 4]);
                MMA3(c[t], ah0, ah1, ah2, ah3, al0, al1, al2, al3, bh0, bh1, bl0, bl1);
            }
        }
        __syncthreads();
    }

    {
        int row0 = mtile * 16 + grp;
#pragma unroll
        for (int t = 0; t < 4; t++) {
            int col0 = (nbase + t) * 8 + 2 * qc;
            Ls[row0 * 65 + col0]           = c[t][0];
            Ls[row0 * 65 + col0 + 1]       = c[t][1];
            Ls[(row0 + 8) * 65 + col0]     = c[t][2];
            Ls[(row0 + 8) * 65 + col0 + 1] = c[t][3];
        }
    }
    __syncthreads();

    if (tid < 64) {
        const float* lrow = &Ls[tid * 65];
        float v0 = -1e30f; int i0 = 0;
#pragma unroll
        for (int e = 0; e < 64; e++) {
            float v = lrow[e];
            if (v > v0) { v0 = v; i0 = e; }
        }
        float v1 = -1e30f; int i1 = 0;
#pragma unroll
        for (int e = 0; e < 64; e++) {
            if (e == i0) continue;
            float v = lrow[e];
            if (v > v1) { v1 = v; i1 = e; }
        }
        float p0 = 1.0f / (1.0f + expf(v1 - v0));
        float p1 = 1.0f - p0;
        int n = tok0 + tid;
        int*   ei = phase ? g_eidx_dn : g_eidx_up;
        float* pr = phase ? g_prob_dn : g_prob_up;
        ei[n * 2 + 0] = i0;
        ei[n * 2 + 1] = i1;
        pr[n * 2 + 0] = p0;
        pr[n * 2 + 1] = p1;
    }
}

// ---------------------------------------------------------------------------
// Up layer (per token): Y = sum_k p_k * (A_e @ X @ B_e^T), X as 32x32.
// dyn smem floats: XtH(1152) XtL(1152) AsH(2304) AsL BsH BsL TsH(2304) TsL
//                  = 16128 floats = 64512 B
// ---------------------------------------------------------------------------
__global__ void up_mma(const float* __restrict__ X,
                       const float* __restrict__ A,
                       const float* __restrict__ Bm,
                       const float* __restrict__ scale,
                       const float* __restrict__ bias)
{
    extern __shared__ float sm[];
    float* XtH = sm;            // 32*36
    float* XtL = sm + 1152;
    float* AsH = sm + 2304;     // 64*36
    float* AsL = sm + 4608;
    float* BsH = sm + 6912;
    float* BsL = sm + 9216;
    float* TsH = sm + 11520;
    float* TsL = sm + 13824;

    const int tid  = threadIdx.x;
    const int w    = tid >> 5;
    const int lane = tid & 31;
    const int grp  = lane >> 2;
    const int qc   = lane & 3;
    const int n    = blockIdx.x;
    const int mtile = w >> 1;
    const int nbase = (w & 1) * 4;

    {
        float4 v = ((const float4*)(X + (size_t)n * 1024))[tid];
        int i = tid >> 3, j0 = (tid & 7) * 4;
        split_tf32(v.x, XtH[(j0 + 0) * 36 + i], XtL[(j0 + 0) * 36 + i]);
        split_tf32(v.y, XtH[(j0 + 1) * 36 + i], XtL[(j0 + 1) * 36 + i]);
        split_tf32(v.z, XtH[(j0 + 2) * 36 + i], XtL[(j0 + 2) * 36 + i]);
        split_tf32(v.w, XtH[(j0 + 3) * 36 + i], XtL[(j0 + 3) * 36 + i]);
    }

    const float sc = scale[0];
    const int   e0 = g_eidx_up[n * 2],  e1 = g_eidx_up[n * 2 + 1];
    const float p0 = g_prob_up[n * 2],  p1 = g_prob_up[n * 2 + 1];

    float c[4][4];
#pragma unroll
    for (int t = 0; t < 4; t++)
#pragma unroll
        for (int q = 0; q < 4; q++) c[t][q] = 0.f;

#pragma unroll 1
    for (int kk2 = 0; kk2 < 2; kk2++) {
        const int   e = kk2 ? e1 : e0;
        const float p = kk2 ? p1 : p0;
        const float* Ag = A  + (size_t)e * 2048;
        const float* Bg = Bm + (size_t)e * 2048;
        __syncthreads();
#pragma unroll
        for (int i = 0; i < 8; i++) {
            int idx = tid + i * 256;
            int row = idx >> 5, col = idx & 31;
            split_tf32(Ag[idx], AsH[row * 36 + col], AsL[row * 36 + col]);
            split_tf32(Bg[idx], BsH[row * 36 + col], BsL[row * 36 + col]);
        }
        __syncthreads();

        // GEMM1: T = A @ X
        float t1[2][4];
#pragma unroll
        for (int t = 0; t < 2; t++)
#pragma unroll
            for (int q = 0; q < 4; q++) t1[t][q] = 0.f;
#pragma unroll
        for (int kk = 0; kk < 4; kk++) {
            int k0 = kk * 8;
            int aoff = (mtile * 16 + grp) * 36 + k0 + qc;
            uint32_t ah0 = FB(AsH[aoff]),     ah1 = FB(AsH[aoff + 8 * 36]);
            uint32_t ah2 = FB(AsH[aoff + 4]), ah3 = FB(AsH[aoff + 8 * 36 + 4]);
            uint32_t al0 = FB(AsL[aoff]),     al1 = FB(AsL[aoff + 8 * 36]);
            uint32_t al2 = FB(AsL[aoff + 4]), al3 = FB(AsL[aoff + 8 * 36 + 4]);
#pragma unroll
            for (int t = 0; t < 2; t++) {
                int boff = (((w & 1) * 2 + t) * 8 + grp) * 36 + k0 + qc;
                uint32_t bh0 = FB(XtH[boff]), bh1 = FB(XtH[boff + 4]);
                uint32_t bl0 = FB(XtL[boff]), bl1 = FB(XtL[boff + 4]);
                MMA3(t1[t], ah0, ah1, ah2, ah3, al0, al1, al2, al3, bh0, bh1, bl0, bl1);
            }
        }
        {
            int row0 = mtile * 16 + grp;
#pragma unroll
            for (int t = 0; t < 2; t++) {
                int col0 = ((w & 1) * 2 + t) * 8 + 2 * qc;
                split_tf32(p * t1[t][0], TsH[row0 * 36 + col0],           TsL[row0 * 36 + col0]);
                split_tf32(p * t1[t][1], TsH[row0 * 36 + col0 + 1],       TsL[row0 * 36 + col0 + 1]);
                split_tf32(p * t1[t][2], TsH[(row0 + 8) * 36 + col0],     TsL[(row0 + 8) * 36 + col0]);
                split_tf32(p * t1[t][3], TsH[(row0 + 8) * 36 + col0 + 1], TsL[(row0 + 8) * 36 + col0 + 1]);
            }
        }
        __syncthreads();

        // GEMM2: Y += T @ B^T
#pragma unroll
        for (int kk = 0; kk < 4; kk++) {
            int k0 = kk * 8;
            int aoff = (mtile * 16 + grp) * 36 + k0 + qc;
            uint32_t ah0 = FB(TsH[aoff]),     ah1 = FB(TsH[aoff + 8 * 36]);
            uint32_t ah2 = FB(TsH[aoff + 4]), ah3 = FB(TsH[aoff + 8 * 36 + 4]);
            uint32_t al0 = FB(TsL[aoff]),     al1 = FB(TsL[aoff + 8 * 36]);
            uint32_t al2 = FB(TsL[aoff + 4]), al3 = FB(TsL[aoff + 8 * 36 + 4]);
#pragma unroll
            for (int t = 0; t < 4; t++) {
                int boff = ((nbase + t) * 8 + grp) * 36 + k0 + qc;
                uint32_t bh0 = FB(BsH[boff]), bh1 = FB(BsH[boff + 4]);
                uint32_t bl0 = FB(BsL[boff]), bl1 = FB(BsL[boff + 4]);
                MMA3(c[t], ah0, ah1, ah2, ah3, al0, al1, al2, al3, bh0, bh1, bl0, bl1);
            }
        }
    }

    // epilogue: scale + bias + exact erf GELU
    float* Hrow = g_h + (size_t)n * 4096;
    const int row0 = mtile * 16 + grp;
#pragma unroll
    for (int t = 0; t < 4; t++) {
        int col0 = (nbase + t) * 8 + 2 * qc;
#pragma unroll
        for (int half = 0; half < 2; half++) {
            int row = row0 + half * 8;
            int oi = row * 64 + col0;
            float y0 = c[t][half * 2 + 0] * sc + bias[oi];
            float y1 = c[t][half * 2 + 1] * sc + bias[oi + 1];
            float g0 = 0.5f * y0 * (1.0f + erff(y0 * 0.70710678118654752f));
            float g1 = 0.5f * y1 * (1.0f + erff(y1 * 0.70710678118654752f));
            *(float2*)(Hrow + oi) = make_float2(g0, g1);
        }
    }
}

// ---------------------------------------------------------------------------
// Down layer (per token): Y = sum_k p_k * (A_e @ H @ B_e^T), H as 64x64.
// dyn smem floats: HtH(4352) HtL AsH(2176) AsL BsH BsL TsH(2176) TsL
//                  = 21760 floats = 87040 B
// ---------------------------------------------------------------------------
__global__ void down_mma(const float* __restrict__ A,
                         const float* __restrict__ Bm,
                         const float* __restrict__ scale,
                         const float* __restrict__ bias,
                         float* __restrict__ out)
{
    extern __shared__ float sm[];
    float* HtH = sm;             // 64*68
    float* HtL = sm + 4352;
    float* AsH = sm + 8704;      // 32*68
    float* AsL = sm + 10880;
    float* BsH = sm + 13056;
    float* BsL = sm + 15232;
    float* TsH = sm + 17408;
    float* TsL = sm + 19584;

    const int tid  = threadIdx.x;
    const int w    = tid >> 5;
    const int lane = tid & 31;
    const int grp  = lane >> 2;
    const int qc   = lane & 3;
    const int n    = blockIdx.x;
    const int mtile  = w & 1;
    const int ntile2 = w >> 1;

    const float* Xrow = g_h + (size_t)n * 4096;
#pragma unroll
    for (int i = 0; i < 16; i++) {
        int idx = tid + i * 256;
        int r = idx >> 6, j = idx & 63;
        split_tf32(Xrow[idx], HtH[j * 68 + r], HtL[j * 68 + r]);
    }

    const float sc = scale[0];
    const int   e0 = g_eidx_dn[n * 2],  e1 = g_eidx_dn[n * 2 + 1];
    const float p0 = g_prob_dn[n * 2],  p1 = g_prob_dn[n * 2 + 1];

    float c[4];
    c[0] = c[1] = c[2] = c[3] = 0.f;

#pragma unroll 1
    for (int kk2 = 0; kk2 < 2; kk2++) {
        const int   e = kk2 ? e1 : e0;
        const float p = kk2 ? p1 : p0;
        const float* Ag = A  + (size_t)e * 2048;
        const float* Bg = Bm + (size_t)e * 2048;
        __syncthreads();
#pragma unroll
        for (int i = 0; i < 8; i++) {
            int idx = tid + i * 256;
            int row = idx >> 6, col = idx & 63;
            split_tf32(Ag[idx], AsH[row * 68 + col], AsL[row * 68 + col]);
            split_tf32(Bg[idx], BsH[row * 68 + col], BsL[row * 68 + col]);
        }
        __syncthreads();

        // GEMM1: T = A @ H
        float t1[2][4];
#pragma unroll
        for (int t = 0; t < 2; t++)
#pragma unroll
            for (int q = 0; q < 4; q++) t1[t][q] = 0.f;
#pragma unroll
        for (int kk = 0; kk < 8; kk++) {
            int k0 = kk * 8;
            int aoff = (mtile * 16 + grp) * 68 + k0 + qc;
            uint32_t ah0 = FB(AsH[aoff]),     ah1 = FB(AsH[aoff + 8 * 68]);
            uint32_t ah2 = FB(AsH[aoff + 4]), ah3 = FB(AsH[aoff + 8 * 68 + 4]);
            uint32_t al0 = FB(AsL[aoff]),     al1 = FB(AsL[aoff + 8 * 68]);
            uint32_t al2 = FB(AsL[aoff + 4]), al3 = FB(AsL[aoff + 8 * 68 + 4]);
#pragma unroll
            for (int t = 0; t < 2; t++) {
                int boff = ((ntile2 * 2 + t) * 8 + grp) * 68 + k0 + qc;
                uint32_t bh0 = FB(HtH[boff]), bh1 = FB(HtH[boff + 4]);
                uint32_t bl0 = FB(HtL[boff]), bl1 = FB(HtL[boff + 4]);
                MMA3(t1[t], ah0, ah1, ah2, ah3, al0, al1, al2, al3, bh0, bh1, bl0, bl1);
            }
        }
        {
            int row0 = mtile * 16 + grp;
#pragma unroll
            for (int t = 0; t < 2; t++) {
                int col0 = (ntile2 * 2 + t) * 8 + 2 * qc;
                split_tf32(p * t1[t][0], TsH[row0 * 68 + col0],           TsL[row0 * 68 + col0]);
                split_tf32(p * t1[t][1], TsH[row0 * 68 + col0 + 1],       TsL[row0 * 68 + col0 + 1]);
                split_tf32(p * t1[t][2], TsH[(row0 + 8) * 68 + col0],     TsL[(row0 + 8) * 68 + col0]);
                split_tf32(p * t1[t][3], TsH[(row0 + 8) * 68 + col0 + 1], TsL[(row0 + 8) * 68 + col0 + 1]);
            }
        }
        __syncthreads();

        // GEMM2: Y += T @ B^T
#pragma unroll
        for (int kk = 0; kk < 8; kk++) {
            int k0 = kk * 8;
            int aoff = (mtile * 16 + grp) * 68 + k0 + qc;
            uint32_t ah0 = FB(TsH[aoff]),     ah1 = FB(TsH[aoff + 8 * 68]);
            uint32_t ah2 = FB(TsH[aoff + 4]), ah3 = FB(TsH[aoff + 8 * 68 + 4]);
            uint32_t al0 = FB(TsL[aoff]),     al1 = FB(TsL[aoff + 8 * 68]);
            uint32_t al2 = FB(TsL[aoff + 4]), al3 = FB(TsL[aoff + 8 * 68 + 4]);
            int boff = (ntile2 * 8 + grp) * 68 + k0 + qc;
            uint32_t bh0 = FB(BsH[boff]), bh1 = FB(BsH[boff + 4]);
            uint32_t bl0 = FB(BsL[boff]), bl1 = FB(BsL[boff + 4]);
            MMA3(c, ah0, ah1, ah2, ah3, al0, al1, al2, al3, bh0, bh1, bl0, bl1);
        }
    }

    float* orow = out + (size_t)n * 1024;
    const int row0 = mtile * 16 + grp;
    const int col0 = ntile2 * 8 + 2 * qc;
#pragma unroll
    for (int half = 0; half < 2; half++) {
        int row = row0 + half * 8;
        int oi = row * 32 + col0;
        float y0 = c[half * 2 + 0] * sc + bias[oi];
        float y1 = c[half * 2 + 1] * sc + bias[oi + 1];
        *(float2*)(orow + oi) = make_float2(y0, y1);
    }
}

// ---------------------------------------------------------------------------
extern "C" void kernel_launch(void* const* d_in, const int* in_sizes, int n_in,
                              void* d_out, int out_size)
{
    const float* x        = (const float*)d_in[0];
    const float* W_up     = (const float*)d_in[1];
    const float* A_up     = (const float*)d_in[2];
    const float* B_up     = (const float*)d_in[3];
    const float* scale_up = (const float*)d_in[4];
    const float* bias_up  = (const float*)d_in[5];
    const float* W_dn     = (const float*)d_in[6];
    const float* A_dn     = (const float*)d_in[7];
    const float* B_dn     = (const float*)d_in[8];
    const float* scale_dn = (const float*)d_in[9];
    const float* bias_dn  = (const float*)d_in[10];
    float* out = (float*)d_out;

    const int N = in_sizes[0] / 1024;   // 8192 tokens

    const int SM_ROUTER = 53504;
    const int SM_UP     = 64512;
    const int SM_DOWN   = 87040;
    cudaFuncSetAttribute(router_mma, cudaFuncAttributeMaxDynamicSharedMemorySize, SM_ROUTER);
    cudaFuncSetAttribute(up_mma,     cudaFuncAttributeMaxDynamicSharedMemorySize, SM_UP);
    cudaFuncSetAttribute(down_mma,   cudaFuncAttributeMaxDynamicSharedMemorySize, SM_DOWN);

    float* hptr = nullptr;
    cudaGetSymbolAddress((void**)&hptr, g_h);

    router_mma<<<N / 64, 256, SM_ROUTER>>>(x, W_up, 1024, 0);
    up_mma<<<N, 256, SM_UP>>>(x, A_up, B_up, scale_up, bias_up);
    router_mma<<<N / 64, 256, SM_ROUTER>>>(hptr, W_dn, 4096, 1);
    down_mma<<<N, 256, SM_DOWN>>>(A_dn, B_dn, scale_dn, bias_dn, out);
}

// round 5
// speedup vs baseline: 1.5018x; 1.2350x over previous
#include <cuda_runtime.h>
#include <math.h>
#include <stdint.h>

// Fixed shapes for this dataset
#define NTOK_MAX 8192

// Scratch (no cudaMalloc allowed)
__device__ float g_h[NTOK_MAX * 4096];        // 128 MB intermediate (post-GELU)
__device__ int   g_eidx_up[NTOK_MAX * 2];
__device__ float g_prob_up[NTOK_MAX * 2];
__device__ int   g_eidx_dn[NTOK_MAX * 2];
__device__ float g_prob_dn[NTOK_MAX * 2];

// round-to-nearest tf32 kept in float container
__device__ __forceinline__ float tf32r(float f) {
    uint32_t u;
    asm("cvt.rna.tf32.f32 %0, %1;" : "=r"(u) : "f"(f));
    return __uint_as_float(u);
}
// split fp32 -> (hi, lo) tf32 pair, as raw bits for mma
__device__ __forceinline__ void sp(float v, uint32_t& h, uint32_t& l) {
    float hf = tf32r(v);
    h = __float_as_uint(hf);
    l = __float_as_uint(tf32r(v - hf));
}

#define MMA_TF32(C, a0, a1, a2, a3, b0, b1)                                    \
    asm volatile(                                                              \
        "mma.sync.aligned.m16n8k8.row.col.f32.tf32.tf32.f32 "                  \
        "{%0,%1,%2,%3},{%4,%5,%6,%7},{%8,%9},{%0,%1,%2,%3};"                   \
        : "+f"((C)[0]), "+f"((C)[1]), "+f"((C)[2]), "+f"((C)[3])               \
        : "r"(a0), "r"(a1), "r"(a2), "r"(a3), "r"(b0), "r"(b1));

// 3xTF32: hi*hi + hi*lo + lo*hi  (lo*lo negligible)
#define MMA3(C, ah0, ah1, ah2, ah3, al0, al1, al2, al3, bh0, bh1, bl0, bl1)    \
    MMA_TF32(C, ah0, ah1, ah2, ah3, bh0, bh1);                                 \
    MMA_TF32(C, ah0, ah1, ah2, ah3, bl0, bl1);                                 \
    MMA_TF32(C, al0, al1, al2, al3, bh0, bh1);

// load+split an A-fragment from row-major tile at [m0+.. rows][k0+.. cols]
#define LDFRAG_A(S, STRIDE, aoff)                                              \
    uint32_t ah0, ah1, ah2, ah3, al0, al1, al2, al3;                           \
    sp((S)[(aoff)],                    ah0, al0);                              \
    sp((S)[(aoff) + 8 * (STRIDE)],     ah1, al1);                              \
    sp((S)[(aoff) + 4],                ah2, al2);                              \
    sp((S)[(aoff) + 8 * (STRIDE) + 4], ah3, al3);

#define LDFRAG_B(S, boff)                                                      \
    uint32_t bh0, bh1, bl0, bl1;                                               \
    sp((S)[(boff)],     bh0, bl0);                                             \
    sp((S)[(boff) + 4], bh1, bl1);

// ---------------------------------------------------------------------------
// Router: logits = X[N,K] @ W[E,K]^T via 3xTF32 mma, then top-2 + softmax(2).
// Block = 64 tokens x 64 experts. 256 threads = 8 warps.
// ---------------------------------------------------------------------------
__global__ void router_mma(const float* __restrict__ X,
                           const float* __restrict__ W,
                           int K, int phase)
{
    __shared__ float Xs[64 * 36];
    __shared__ float Ws[64 * 36];
    __shared__ float Ls[64 * 65];

    const int tid  = threadIdx.x;
    const int w    = tid >> 5;
    const int lane = tid & 31;
    const int grp  = lane >> 2;
    const int qc   = lane & 3;
    const int tok0 = blockIdx.x * 64;
    const int mtile = w >> 1;
    const int nbase = (w & 1) * 4;

    float c[4][4];
#pragma unroll
    for (int t = 0; t < 4; t++)
#pragma unroll
        for (int q = 0; q < 4; q++) c[t][q] = 0.f;

    for (int kt = 0; kt < K; kt += 32) {
        // vectorized stage: 64 rows x 32 cols each, float4
#pragma unroll
        for (int i = 0; i < 2; i++) {
            int idx4 = tid + i * 256;            // 0..511
            int row = idx4 >> 3, c4 = idx4 & 7;
            *(float4*)&Xs[row * 36 + c4 * 4] =
                *(const float4*)&X[(size_t)(tok0 + row) * K + kt + c4 * 4];
            *(float4*)&Ws[row * 36 + c4 * 4] =
                *(const float4*)&W[(size_t)row * K + kt + c4 * 4];
        }
        __syncthreads();
#pragma unroll
        for (int kk = 0; kk < 4; kk++) {
            int k0 = kk * 8;
            int aoff = (mtile * 16 + grp) * 36 + k0 + qc;
            LDFRAG_A(Xs, 36, aoff);
#pragma unroll
            for (int t = 0; t < 4; t++) {
                int boff = ((nbase + t) * 8 + grp) * 36 + k0 + qc;
                LDFRAG_B(Ws, boff);
                MMA3(c[t], ah0, ah1, ah2, ah3, al0, al1, al2, al3, bh0, bh1, bl0, bl1);
            }
        }
        __syncthreads();
    }

    {
        int row0 = mtile * 16 + grp;
#pragma unroll
        for (int t = 0; t < 4; t++) {
            int col0 = (nbase + t) * 8 + 2 * qc;
            Ls[row0 * 65 + col0]           = c[t][0];
            Ls[row0 * 65 + col0 + 1]       = c[t][1];
            Ls[(row0 + 8) * 65 + col0]     = c[t][2];
            Ls[(row0 + 8) * 65 + col0 + 1] = c[t][3];
        }
    }
    __syncthreads();

    if (tid < 64) {
        const float* lrow = &Ls[tid * 65];
        float v0 = -1e30f; int i0 = 0;
#pragma unroll
        for (int e = 0; e < 64; e++) {
            float v = lrow[e];
            if (v > v0) { v0 = v; i0 = e; }
        }
        float v1 = -1e30f; int i1 = 0;
#pragma unroll
        for (int e = 0; e < 64; e++) {
            if (e == i0) continue;
            float v = lrow[e];
            if (v > v1) { v1 = v; i1 = e; }
        }
        float p0 = 1.0f / (1.0f + expf(v1 - v0));
        float p1 = 1.0f - p0;
        int n = tok0 + tid;
        int*   ei = phase ? g_eidx_dn : g_eidx_up;
        float* pr = phase ? g_prob_dn : g_prob_up;
        ei[n * 2 + 0] = i0;
        ei[n * 2 + 1] = i1;
        pr[n * 2 + 0] = p0;
        pr[n * 2 + 1] = p1;
    }
}

// ---------------------------------------------------------------------------
// Up layer (per token): Y = sum_k p_k * (A_e @ X @ B_e^T), X as 32x32 [i][j].
// GEMM1: T[64,32] = A[64,32] @ X[32,32]   (X row-major, read as col-major B-op)
// GEMM2: Y[64,64] += T[64,32] @ B[64,32]^T
// smem: Xs 32x36 + As/Bs/Ts 64x36 = 32.3 KB.  256 threads = 8 warps.
// ---------------------------------------------------------------------------
__global__ void up_mma(const float* __restrict__ X,
                       const float* __restrict__ A,
                       const float* __restrict__ Bm,
                       const float* __restrict__ scale,
                       const float* __restrict__ bias)
{
    __shared__ float Xs[32 * 36];   // [i][j] row-major
    __shared__ float As[64 * 36];   // A[o][i]
    __shared__ float Bs[64 * 36];   // B[p][j]
    __shared__ float Ts[64 * 36];   // T[o][j] (prob-scaled, fp32)

    const int tid  = threadIdx.x;
    const int w    = tid >> 5;
    const int lane = tid & 31;
    const int grp  = lane >> 2;
    const int qc   = lane & 3;
    const int n    = blockIdx.x;
    const int mtile = w >> 1;
    const int nbase = (w & 1) * 4;

    // load X row as 32x32 [i][j], coalesced float4
    {
        int i = tid >> 3, j4 = tid & 7;
        *(float4*)&Xs[i * 36 + j4 * 4] =
            *(const float4*)&X[(size_t)n * 1024 + i * 32 + j4 * 4];
    }

    const float sc = scale[0];
    const int   e0 = g_eidx_up[n * 2],  e1 = g_eidx_up[n * 2 + 1];
    const float p0 = g_prob_up[n * 2],  p1 = g_prob_up[n * 2 + 1];

    float c[4][4];
#pragma unroll
    for (int t = 0; t < 4; t++)
#pragma unroll
        for (int q = 0; q < 4; q++) c[t][q] = 0.f;

#pragma unroll 1
    for (int kk2 = 0; kk2 < 2; kk2++) {
        const int   e = kk2 ? e1 : e0;
        const float p = kk2 ? p1 : p0;
        const float* Ag = A  + (size_t)e * 2048;
        const float* Bg = Bm + (size_t)e * 2048;
        __syncthreads();
#pragma unroll
        for (int i = 0; i < 2; i++) {
            int idx4 = tid + i * 256;           // 0..511 (2048 floats)
            int row = idx4 >> 3, c4 = idx4 & 7;
            *(float4*)&As[row * 36 + c4 * 4] = *(const float4*)&Ag[idx4 * 4];
            *(float4*)&Bs[row * 36 + c4 * 4] = *(const float4*)&Bg[idx4 * 4];
        }
        __syncthreads();

        // GEMM1: T = A @ X ; warp: mtile rows, n-tiles (w&1)*2 + {0,1}
        float t1[2][4];
#pragma unroll
        for (int t = 0; t < 2; t++)
#pragma unroll
            for (int q = 0; q < 4; q++) t1[t][q] = 0.f;
#pragma unroll
        for (int kk = 0; kk < 4; kk++) {
            int k0 = kk * 8;
            int aoff = (mtile * 16 + grp) * 36 + k0 + qc;
            LDFRAG_A(As, 36, aoff);
#pragma unroll
            for (int t = 0; t < 2; t++) {
                // B-op = X col-major (k=i, n=j): addr (k0+qc)*36 + n0+grp
                int boff = (k0 + qc) * 36 + ((w & 1) * 2 + t) * 8 + grp;
                uint32_t bh0, bh1, bl0, bl1;
                sp(Xs[boff],          bh0, bl0);
                sp(Xs[boff + 4 * 36], bh1, bl1);
                MMA3(t1[t], ah0, ah1, ah2, ah3, al0, al1, al2, al3, bh0, bh1, bl0, bl1);
            }
        }
        {
            int row0 = mtile * 16 + grp;
#pragma unroll
            for (int t = 0; t < 2; t++) {
                int col0 = ((w & 1) * 2 + t) * 8 + 2 * qc;
                *(float2*)&Ts[row0 * 36 + col0]       = make_float2(p * t1[t][0], p * t1[t][1]);
                *(float2*)&Ts[(row0 + 8) * 36 + col0] = make_float2(p * t1[t][2], p * t1[t][3]);
            }
        }
        __syncthreads();

        // GEMM2: Y += T @ B^T
#pragma unroll
        for (int kk = 0; kk < 4; kk++) {
            int k0 = kk * 8;
            int aoff = (mtile * 16 + grp) * 36 + k0 + qc;
            LDFRAG_A(Ts, 36, aoff);
#pragma unroll
            for (int t = 0; t < 4; t++) {
                int boff = ((nbase + t) * 8 + grp) * 36 + k0 + qc;
                LDFRAG_B(Bs, boff);
                MMA3(c[t], ah0, ah1, ah2, ah3, al0, al1, al2, al3, bh0, bh1, bl0, bl1);
            }
        }
    }

    // epilogue: scale + bias + exact erf GELU
    float* Hrow = g_h + (size_t)n * 4096;
    const int row0 = mtile * 16 + grp;
#pragma unroll
    for (int t = 0; t < 4; t++) {
        int col0 = (nbase + t) * 8 + 2 * qc;
#pragma unroll
        for (int half = 0; half < 2; half++) {
            int row = row0 + half * 8;
            int oi = row * 64 + col0;
            float y0 = c[t][half * 2 + 0] * sc + bias[oi];
            float y1 = c[t][half * 2 + 1] * sc + bias[oi + 1];
            float g0 = 0.5f * y0 * (1.0f + erff(y0 * 0.70710678118654752f));
            float g1 = 0.5f * y1 * (1.0f + erff(y1 * 0.70710678118654752f));
            *(float2*)(Hrow + oi) = make_float2(g0, g1);
        }
    }
}

// ---------------------------------------------------------------------------
// Down layer (per token): Y = sum_k p_k * (A_e @ H @ B_e^T), H as 64x64 [i][j].
// GEMM1: T[32,64] = A[32,64] @ H[64,64]  (H row-major, read as col-major B-op)
// GEMM2: Y[32,32] += T[32,64] @ B[32,64]^T
// smem: Hs 64x68 + As/Bs/Ts 32x68 = 43.5 KB.
// ---------------------------------------------------------------------------
__global__ void down_mma(const float* __restrict__ A,
                         const float* __restrict__ Bm,
                         const float* __restrict__ scale,
                         const float* __restrict__ bias,
                         float* __restrict__ out)
{
    __shared__ float Hs[64 * 68];   // [i][j] row-major
    __shared__ float As[32 * 68];   // A[o][i]
    __shared__ float Bs[32 * 68];   // B[p][j]
    __shared__ float Ts[32 * 68];   // T[o][j] (prob-scaled, fp32)

    const int tid  = threadIdx.x;
    const int w    = tid >> 5;
    const int lane = tid & 31;
    const int grp  = lane >> 2;
    const int qc   = lane & 3;
    const int n    = blockIdx.x;
    const int mtile  = w & 1;
    const int ntile2 = w >> 1;

    // load H row as 64x64 [i][j], coalesced float4
    const float* Xrow = g_h + (size_t)n * 4096;
#pragma unroll
    for (int i = 0; i < 4; i++) {
        int idx4 = tid + i * 256;               // 0..1023
        int r = idx4 >> 4, j4 = idx4 & 15;
        *(float4*)&Hs[r * 68 + j4 * 4] = *(const float4*)&Xrow[idx4 * 4];
    }

    const float sc = scale[0];
    const int   e0 = g_eidx_dn[n * 2],  e1 = g_eidx_dn[n * 2 + 1];
    const float p0 = g_prob_dn[n * 2],  p1 = g_prob_dn[n * 2 + 1];

    float c[4];
    c[0] = c[1] = c[2] = c[3] = 0.f;

#pragma unroll 1
    for (int kk2 = 0; kk2 < 2; kk2++) {
        const int   e = kk2 ? e1 : e0;
        const float p = kk2 ? p1 : p0;
        const float* Ag = A  + (size_t)e * 2048;
        const float* Bg = Bm + (size_t)e * 2048;
        __syncthreads();
#pragma unroll
        for (int i = 0; i < 2; i++) {
            int idx4 = tid + i * 256;           // 0..511 (2048 floats, 32x64)
            int row = idx4 >> 4, c4 = idx4 & 15;
            *(float4*)&As[row * 68 + c4 * 4] = *(const float4*)&Ag[idx4 * 4];
            *(float4*)&Bs[row * 68 + c4 * 4] = *(const float4*)&Bg[idx4 * 4];
        }
        __syncthreads();

        // GEMM1: T = A @ H ; warp: mtile rows, n-tiles ntile2*2 + {0,1}
        float t1[2][4];
#pragma unroll
        for (int t = 0; t < 2; t++)
#pragma unroll
            for (int q = 0; q < 4; q++) t1[t][q] = 0.f;
#pragma unroll
        for (int kk = 0; kk < 8; kk++) {
            int k0 = kk * 8;
            int aoff = (mtile * 16 + grp) * 68 + k0 + qc;
            LDFRAG_A(As, 68, aoff);
#pragma unroll
            for (int t = 0; t < 2; t++) {
                // B-op = H col-major (k=i, n=j): addr (k0+qc)*68 + n0+grp
                int boff = (k0 + qc) * 68 + (ntile2 * 2 + t) * 8 + grp;
                uint32_t bh0, bh1, bl0, bl1;
                sp(Hs[boff],          bh0, bl0);
                sp(Hs[boff + 4 * 68], bh1, bl1);
                MMA3(t1[t], ah0, ah1, ah2, ah3, al0, al1, al2, al3, bh0, bh1, bl0, bl1);
            }
        }
        {
            int row0 = mtile * 16 + grp;
#pragma unroll
            for (int t = 0; t < 2; t++) {
                int col0 = (ntile2 * 2 + t) * 8 + 2 * qc;
                *(float2*)&Ts[row0 * 68 + col0]       = make_float2(p * t1[t][0], p * t1[t][1]);
                *(float2*)&Ts[(row0 + 8) * 68 + col0] = make_float2(p * t1[t][2], p * t1[t][3]);
            }
        }
        __syncthreads();

        // GEMM2: Y += T @ B^T
#pragma unroll
        for (int kk = 0; kk < 8; kk++) {
            int k0 = kk * 8;
            int aoff = (mtile * 16 + grp) * 68 + k0 + qc;
            LDFRAG_A(Ts, 68, aoff);
            int boff = (ntile2 * 8 + grp) * 68 + k0 + qc;
            LDFRAG_B(Bs, boff);
            MMA3(c, ah0, ah1, ah2, ah3, al0, al1, al2, al3, bh0, bh1, bl0, bl1);
        }
    }

    float* orow = out + (size_t)n * 1024;
    const int row0 = mtile * 16 + grp;
    const int col0 = ntile2 * 8 + 2 * qc;
#pragma unroll
    for (int half = 0; half < 2; half++) {
        int row = row0 + half * 8;
        int oi = row * 32 + col0;
        float y0 = c[half * 2 + 0] * sc + bias[oi];
        float y1 = c[half * 2 + 1] * sc + bias[oi + 1];
        *(float2*)(orow + oi) = make_float2(y0, y1);
    }
}

// ---------------------------------------------------------------------------
extern "C" void kernel_launch(void* const* d_in, const int* in_sizes, int n_in,
                              void* d_out, int out_size)
{
    const float* x        = (const float*)d_in[0];
    const float* W_up     = (const float*)d_in[1];
    const float* A_up     = (const float*)d_in[2];
    const float* B_up     = (const float*)d_in[3];
    const float* scale_up = (const float*)d_in[4];
    const float* bias_up  = (const float*)d_in[5];
    const float* W_dn     = (const float*)d_in[6];
    const float* A_dn     = (const float*)d_in[7];
    const float* B_dn     = (const float*)d_in[8];
    const float* scale_dn = (const float*)d_in[9];
    const float* bias_dn  = (const float*)d_in[10];
    float* out = (float*)d_out;

    const int N = in_sizes[0] / 1024;   // 8192 tokens

    float* hptr = nullptr;
    cudaGetSymbolAddress((void**)&hptr, g_h);

    router_mma<<<N / 64, 256>>>(x, W_up, 1024, 0);
    up_mma<<<N, 256>>>(x, A_up, B_up, scale_up, bias_up);
    router_mma<<<N / 64, 256>>>(hptr, W_dn, 4096, 1);
    down_mma<<<N, 256>>>(A_dn, B_dn, scale_dn, bias_dn, out);
}

// round 6
// speedup vs baseline: 1.8609x; 1.2391x over previous
#include <cuda_runtime.h>
#include <math.h>
#include <stdint.h>

// Fixed shapes for this dataset
#define NTOK_MAX 8192

// Scratch (no cudaMalloc allowed)
__device__ float g_h[NTOK_MAX * 4096];        // 128 MB intermediate (post-GELU)
__device__ int   g_eidx_up[NTOK_MAX * 2];
__device__ float g_prob_up[NTOK_MAX * 2];
__device__ int   g_eidx_dn[NTOK_MAX * 2];
__device__ float g_prob_dn[NTOK_MAX * 2];

// Truncation split fp32 -> (hi, lo) tf32 pair (raw fp32-layout bits for mma).
// hi = top mantissa bits (LOP3), lo = v - hi (EXACT: residual fits fp32).
// MMA consumes fp32-layout registers truncated to tf32, so no cvt needed.
__device__ __forceinline__ void sp(float v, uint32_t& h, uint32_t& l) {
    uint32_t hb = __float_as_uint(v) & 0xFFFFE000u;
    h = hb;
    l = __float_as_uint(v - __uint_as_float(hb));
}

#define MMA_TF32(C, a0, a1, a2, a3, b0, b1)                                    \
    asm volatile(                                                              \
        "mma.sync.aligned.m16n8k8.row.col.f32.tf32.tf32.f32 "                  \
        "{%0,%1,%2,%3},{%4,%5,%6,%7},{%8,%9},{%0,%1,%2,%3};"                   \
        : "+f"((C)[0]), "+f"((C)[1]), "+f"((C)[2]), "+f"((C)[3])               \
        : "r"(a0), "r"(a1), "r"(a2), "r"(a3), "r"(b0), "r"(b1));

// 3xTF32: hi*hi + hi*lo + lo*hi  (lo*lo negligible)
#define MMA3(C, ah0, ah1, ah2, ah3, al0, al1, al2, al3, bh0, bh1, bl0, bl1)    \
    MMA_TF32(C, ah0, ah1, ah2, ah3, bh0, bh1);                                 \
    MMA_TF32(C, ah0, ah1, ah2, ah3, bl0, bl1);                                 \
    MMA_TF32(C, al0, al1, al2, al3, bh0, bh1);

// load+split an A-fragment from row-major tile at [m0+.. rows][k0+.. cols]
#define LDFRAG_A(S, STRIDE, aoff)                                              \
    uint32_t ah0, ah1, ah2, ah3, al0, al1, al2, al3;                           \
    sp((S)[(aoff)],                    ah0, al0);                              \
    sp((S)[(aoff) + 8 * (STRIDE)],     ah1, al1);                              \
    sp((S)[(aoff) + 4],                ah2, al2);                              \
    sp((S)[(aoff) + 8 * (STRIDE) + 4], ah3, al3);

#define LDFRAG_B(S, boff)                                                      \
    uint32_t bh0, bh1, bl0, bl1;                                               \
    sp((S)[(boff)],     bh0, bl0);                                             \
    sp((S)[(boff) + 4], bh1, bl1);

// ---------------------------------------------------------------------------
// Router: logits = X[N,K] @ W[E,K]^T via 3xTF32 mma, then top-2 + softmax(2).
// Block = 64 tokens x 64 experts. 256 threads = 8 warps.
// ---------------------------------------------------------------------------
__global__ void router_mma(const float* __restrict__ X,
                           const float* __restrict__ W,
                           int K, int phase)
{
    __shared__ float Xs[64 * 36];
    __shared__ float Ws[64 * 36];
    __shared__ float Ls[64 * 65];

    const int tid  = threadIdx.x;
    const int w    = tid >> 5;
    const int lane = tid & 31;
    const int grp  = lane >> 2;
    const int qc   = lane & 3;
    const int tok0 = blockIdx.x * 64;
    const int mtile = w >> 1;
    const int nbase = (w & 1) * 4;

    float c[4][4];
#pragma unroll
    for (int t = 0; t < 4; t++)
#pragma unroll
        for (int q = 0; q < 4; q++) c[t][q] = 0.f;

    for (int kt = 0; kt < K; kt += 32) {
        // vectorized stage: 64 rows x 32 cols each, float4
#pragma unroll
        for (int i = 0; i < 2; i++) {
            int idx4 = tid + i * 256;            // 0..511
            int row = idx4 >> 3, c4 = idx4 & 7;
            *(float4*)&Xs[row * 36 + c4 * 4] =
                *(const float4*)&X[(size_t)(tok0 + row) * K + kt + c4 * 4];
            *(float4*)&Ws[row * 36 + c4 * 4] =
                *(const float4*)&W[(size_t)row * K + kt + c4 * 4];
        }
        __syncthreads();
#pragma unroll
        for (int kk = 0; kk < 4; kk++) {
            int k0 = kk * 8;
            int aoff = (mtile * 16 + grp) * 36 + k0 + qc;
            LDFRAG_A(Xs, 36, aoff);
#pragma unroll
            for (int t = 0; t < 4; t++) {
                int boff = ((nbase + t) * 8 + grp) * 36 + k0 + qc;
                LDFRAG_B(Ws, boff);
                MMA3(c[t], ah0, ah1, ah2, ah3, al0, al1, al2, al3, bh0, bh1, bl0, bl1);
            }
        }
        __syncthreads();
    }

    {
        int row0 = mtile * 16 + grp;
#pragma unroll
        for (int t = 0; t < 4; t++) {
            int col0 = (nbase + t) * 8 + 2 * qc;
            Ls[row0 * 65 + col0]           = c[t][0];
            Ls[row0 * 65 + col0 + 1]       = c[t][1];
            Ls[(row0 + 8) * 65 + col0]     = c[t][2];
            Ls[(row0 + 8) * 65 + col0 + 1] = c[t][3];
        }
    }
    __syncthreads();

    if (tid < 64) {
        const float* lrow = &Ls[tid * 65];
        float v0 = -1e30f; int i0 = 0;
#pragma unroll
        for (int e = 0; e < 64; e++) {
            float v = lrow[e];
            if (v > v0) { v0 = v; i0 = e; }
        }
        float v1 = -1e30f; int i1 = 0;
#pragma unroll
        for (int e = 0; e < 64; e++) {
            if (e == i0) continue;
            float v = lrow[e];
            if (v > v1) { v1 = v; i1 = e; }
        }
        float p0 = 1.0f / (1.0f + expf(v1 - v0));
        float p1 = 1.0f - p0;
        int n = tok0 + tid;
        int*   ei = phase ? g_eidx_dn : g_eidx_up;
        float* pr = phase ? g_prob_dn : g_prob_up;
        ei[n * 2 + 0] = i0;
        ei[n * 2 + 1] = i1;
        pr[n * 2 + 0] = p0;
        pr[n * 2 + 1] = p1;
    }
}

// ---------------------------------------------------------------------------
// Up layer (per token): Y = sum_k p_k * (A_e @ X @ B_e^T), X as 32x32 [i][j].
// GEMM1: T[64,32] = A[64,32] @ X[32,32]   (X row-major, read as col-major B-op)
// GEMM2: Y[64,64] += T[64,32] @ B[64,32]^T
// smem: Xs 32x36 + As/Bs/Ts 64x36 = 32.3 KB.  256 threads = 8 warps.
// ---------------------------------------------------------------------------
__global__ void up_mma(const float* __restrict__ X,
                       const float* __restrict__ A,
                       const float* __restrict__ Bm,
                       const float* __restrict__ scale,
                       const float* __restrict__ bias)
{
    __shared__ float Xs[32 * 36];   // [i][j] row-major
    __shared__ float As[64 * 36];   // A[o][i]
    __shared__ float Bs[64 * 36];   // B[p][j]
    __shared__ float Ts[64 * 36];   // T[o][j] (prob-scaled, fp32)

    const int tid  = threadIdx.x;
    const int w    = tid >> 5;
    const int lane = tid & 31;
    const int grp  = lane >> 2;
    const int qc   = lane & 3;
    const int n    = blockIdx.x;
    const int mtile = w >> 1;
    const int nbase = (w & 1) * 4;

    // load X row as 32x32 [i][j], coalesced float4
    {
        int i = tid >> 3, j4 = tid & 7;
        *(float4*)&Xs[i * 36 + j4 * 4] =
            *(const float4*)&X[(size_t)n * 1024 + i * 32 + j4 * 4];
    }

    const float sc = scale[0];
    const int   e0 = g_eidx_up[n * 2],  e1 = g_eidx_up[n * 2 + 1];
    const float p0 = g_prob_up[n * 2],  p1 = g_prob_up[n * 2 + 1];

    float c[4][4];
#pragma unroll
    for (int t = 0; t < 4; t++)
#pragma unroll
        for (int q = 0; q < 4; q++) c[t][q] = 0.f;

#pragma unroll 1
    for (int kk2 = 0; kk2 < 2; kk2++) {
        const int   e = kk2 ? e1 : e0;
        const float p = kk2 ? p1 : p0;
        const float* Ag = A  + (size_t)e * 2048;
        const float* Bg = Bm + (size_t)e * 2048;
        __syncthreads();
#pragma unroll
        for (int i = 0; i < 2; i++) {
            int idx4 = tid + i * 256;           // 0..511 (2048 floats)
            int row = idx4 >> 3, c4 = idx4 & 7;
            *(float4*)&As[row * 36 + c4 * 4] = *(const float4*)&Ag[idx4 * 4];
            *(float4*)&Bs[row * 36 + c4 * 4] = *(const float4*)&Bg[idx4 * 4];
        }
        __syncthreads();

        // GEMM1: T = A @ X ; warp: mtile rows, n-tiles (w&1)*2 + {0,1}
        float t1[2][4];
#pragma unroll
        for (int t = 0; t < 2; t++)
#pragma unroll
            for (int q = 0; q < 4; q++) t1[t][q] = 0.f;
#pragma unroll
        for (int kk = 0; kk < 4; kk++) {
            int k0 = kk * 8;
            int aoff = (mtile * 16 + grp) * 36 + k0 + qc;
            LDFRAG_A(As, 36, aoff);
#pragma unroll
            for (int t = 0; t < 2; t++) {
                // B-op = X col-major (k=i, n=j): addr (k0+qc)*36 + n0+grp
                int boff = (k0 + qc) * 36 + ((w & 1) * 2 + t) * 8 + grp;
                uint32_t bh0, bh1, bl0, bl1;
                sp(Xs[boff],          bh0, bl0);
                sp(Xs[boff + 4 * 36], bh1, bl1);
                MMA3(t1[t], ah0, ah1, ah2, ah3, al0, al1, al2, al3, bh0, bh1, bl0, bl1);
            }
        }
        {
            int row0 = mtile * 16 + grp;
#pragma unroll
            for (int t = 0; t < 2; t++) {
                int col0 = ((w & 1) * 2 + t) * 8 + 2 * qc;
                *(float2*)&Ts[row0 * 36 + col0]       = make_float2(p * t1[t][0], p * t1[t][1]);
                *(float2*)&Ts[(row0 + 8) * 36 + col0] = make_float2(p * t1[t][2], p * t1[t][3]);
            }
        }
        __syncthreads();

        // GEMM2: Y += T @ B^T
#pragma unroll
        for (int kk = 0; kk < 4; kk++) {
            int k0 = kk * 8;
            int aoff = (mtile * 16 + grp) * 36 + k0 + qc;
            LDFRAG_A(Ts, 36, aoff);
#pragma unroll
            for (int t = 0; t < 4; t++) {
                int boff = ((nbase + t) * 8 + grp) * 36 + k0 + qc;
                LDFRAG_B(Bs, boff);
                MMA3(c[t], ah0, ah1, ah2, ah3, al0, al1, al2, al3, bh0, bh1, bl0, bl1);
            }
        }
    }

    // epilogue: scale + bias + exact erf GELU
    float* Hrow = g_h + (size_t)n * 4096;
    const int row0 = mtile * 16 + grp;
#pragma unroll
    for (int t = 0; t < 4; t++) {
        int col0 = (nbase + t) * 8 + 2 * qc;
#pragma unroll
        for (int half = 0; half < 2; half++) {
            int row = row0 + half * 8;
            int oi = row * 64 + col0;
            float y0 = c[t][half * 2 + 0] * sc + bias[oi];
            float y1 = c[t][half * 2 + 1] * sc + bias[oi + 1];
            float g0 = 0.5f * y0 * (1.0f + erff(y0 * 0.70710678118654752f));
            float g1 = 0.5f * y1 * (1.0f + erff(y1 * 0.70710678118654752f));
            *(float2*)(Hrow + oi) = make_float2(g0, g1);
        }
    }
}

// ---------------------------------------------------------------------------
// Down layer (per token): Y = sum_k p_k * (A_e @ H @ B_e^T), H as 64x64 [i][j].
// GEMM1: T[32,64] = A[32,64] @ H[64,64]  (H row-major, read as col-major B-op)
// GEMM2: Y[32,32] += T[32,64] @ B[32,64]^T
// smem: Hs 64x68 + As/Bs/Ts 32x68 = 43.5 KB.
// ---------------------------------------------------------------------------
__global__ void down_mma(const float* __restrict__ A,
                         const float* __restrict__ Bm,
                         const float* __restrict__ scale,
                         const float* __restrict__ bias,
                         float* __restrict__ out)
{
    __shared__ float Hs[64 * 68];   // [i][j] row-major
    __shared__ float As[32 * 68];   // A[o][i]
    __shared__ float Bs[32 * 68];   // B[p][j]
    __shared__ float Ts[32 * 68];   // T[o][j] (prob-scaled, fp32)

    const int tid  = threadIdx.x;
    const int w    = tid >> 5;
    const int lane = tid & 31;
    const int grp  = lane >> 2;
    const int qc   = lane & 3;
    const int n    = blockIdx.x;
    const int mtile  = w & 1;
    const int ntile2 = w >> 1;

    // load H row as 64x64 [i][j], coalesced float4
    const float* Xrow = g_h + (size_t)n * 4096;
#pragma unroll
    for (int i = 0; i < 4; i++) {
        int idx4 = tid + i * 256;               // 0..1023
        int r = idx4 >> 4, j4 = idx4 & 15;
        *(float4*)&Hs[r * 68 + j4 * 4] = *(const float4*)&Xrow[idx4 * 4];
    }

    const float sc = scale[0];
    const int   e0 = g_eidx_dn[n * 2],  e1 = g_eidx_dn[n * 2 + 1];
    const float p0 = g_prob_dn[n * 2],  p1 = g_prob_dn[n * 2 + 1];

    float c[4];
    c[0] = c[1] = c[2] = c[3] = 0.f;

#pragma unroll 1
    for (int kk2 = 0; kk2 < 2; kk2++) {
        const int   e = kk2 ? e1 : e0;
        const float p = kk2 ? p1 : p0;
        const float* Ag = A  + (size_t)e * 2048;
        const float* Bg = Bm + (size_t)e * 2048;
        __syncthreads();
#pragma unroll
        for (int i = 0; i < 2; i++) {
            int idx4 = tid + i * 256;           // 0..511 (2048 floats, 32x64)
            int row = idx4 >> 4, c4 = idx4 & 15;
            *(float4*)&As[row * 68 + c4 * 4] = *(const float4*)&Ag[idx4 * 4];
            *(float4*)&Bs[row * 68 + c4 * 4] = *(const float4*)&Bg[idx4 * 4];
        }
        __syncthreads();

        // GEMM1: T = A @ H ; warp: mtile rows, n-tiles ntile2*2 + {0,1}
        float t1[2][4];
#pragma unroll
        for (int t = 0; t < 2; t++)
#pragma unroll
            for (int q = 0; q < 4; q++) t1[t][q] = 0.f;
#pragma unroll
        for (int kk = 0; kk < 8; kk++) {
            int k0 = kk * 8;
            int aoff = (mtile * 16 + grp) * 68 + k0 + qc;
            LDFRAG_A(As, 68, aoff);
#pragma unroll
            for (int t = 0; t < 2; t++) {
                // B-op = H col-major (k=i, n=j): addr (k0+qc)*68 + n0+grp
                int boff = (k0 + qc) * 68 + (ntile2 * 2 + t) * 8 + grp;
                uint32_t bh0, bh1, bl0, bl1;
                sp(Hs[boff],          bh0, bl0);
                sp(Hs[boff + 4 * 68], bh1, bl1);
                MMA3(t1[t], ah0, ah1, ah2, ah3, al0, al1, al2, al3, bh0, bh1, bl0, bl1);
            }
        }
        {
            int row0 = mtile * 16 + grp;
#pragma unroll
            for (int t = 0; t < 2; t++) {
                int col0 = (ntile2 * 2 + t) * 8 + 2 * qc;
                *(float2*)&Ts[row0 * 68 + col0]       = make_float2(p * t1[t][0], p * t1[t][1]);
                *(float2*)&Ts[(row0 + 8) * 68 + col0] = make_float2(p * t1[t][2], p * t1[t][3]);
            }
        }
        __syncthreads();

        // GEMM2: Y += T @ B^T
#pragma unroll
        for (int kk = 0; kk < 8; kk++) {
            int k0 = kk * 8;
            int aoff = (mtile * 16 + grp) * 68 + k0 + qc;
            LDFRAG_A(Ts, 68, aoff);
            int boff = (ntile2 * 8 + grp) * 68 + k0 + qc;
            LDFRAG_B(Bs, boff);
            MMA3(c, ah0, ah1, ah2, ah3, al0, al1, al2, al3, bh0, bh1, bl0, bl1);
        }
    }

    float* orow = out + (size_t)n * 1024;
    const int row0 = mtile * 16 + grp;
    const int col0 = ntile2 * 8 + 2 * qc;
#pragma unroll
    for (int half = 0; half < 2; half++) {
        int row = row0 + half * 8;
        int oi = row * 32 + col0;
        float y0 = c[half * 2 + 0] * sc + bias[oi];
        float y1 = c[half * 2 + 1] * sc + bias[oi + 1];
        *(float2*)(orow + oi) = make_float2(y0, y1);
    }
}

// ---------------------------------------------------------------------------
extern "C" void kernel_launch(void* const* d_in, const int* in_sizes, int n_in,
                              void* d_out, int out_size)
{
    const float* x        = (const float*)d_in[0];
    const float* W_up     = (const float*)d_in[1];
    const float* A_up     = (const float*)d_in[2];
    const float* B_up     = (const float*)d_in[3];
    const float* scale_up = (const float*)d_in[4];
    const float* bias_up  = (const float*)d_in[5];
    const float* W_dn     = (const float*)d_in[6];
    const float* A_dn     = (const float*)d_in[7];
    const float* B_dn     = (const float*)d_in[8];
    const float* scale_dn = (const float*)d_in[9];
    const float* bias_dn  = (const float*)d_in[10];
    float* out = (float*)d_out;

    const int N = in_sizes[0] / 1024;   // 8192 tokens

    float* hptr = nullptr;
    cudaGetSymbolAddress((void**)&hptr, g_h);

    router_mma<<<N / 64, 256>>>(x, W_up, 1024, 0);
    up_mma<<<N, 256>>>(x, A_up, B_up, scale_up, bias_up);
    router_mma<<<N / 64, 256>>>(hptr, W_dn, 4096, 1);
    down_mma<<<N, 256>>>(A_dn, B_dn, scale_dn, bias_dn, out);
}